// round 15
// baseline (speedup 1.0000x reference)
#include <cuda_runtime.h>
#include <cuda_fp16.h>
#include <cstdint>

#define SEQ   256
#define HID   512
#define NOUT  128
#define NB    512
#define NBLK  128          // 4 pair-tiles x 32 j-tiles; each CTA runs 2 chains of 64 rows
#define NTHR  256

// SMEM regions (bytes from dynamic base)
#define A0_OFF    0u       // 64 KB A tile chain 0 (64 rows x 1024B, swizzled)
#define A1_OFF    65536u   // 64 KB A tile chain 1
#define ST0_OFF   131072u  // 2 KB h staging chain 0
#define ST1_OFF   133120u  // 2 KB h staging chain 1
#define DYN_SMEM  135168

// ------------------------- device globals (scratch) --------------------------
__device__ __half  g_hbuf[2][NB * HID];   // ping-pong h (fp16, row-major [batch][hid])
__device__ float   g_hfin[NB * HID];      // final h (fp32) for projection
__device__ unsigned g_leaf[8][8 * 32];    // per-group leaf counters (8 groups of 64 rows)
__device__ unsigned g_rootc[8 * 32];      // per-group root counter
__device__ unsigned g_genm[8 * 32];       // per-group generation

// ------------------------------ PTX helpers ----------------------------------
__device__ __forceinline__ uint32_t smem_u32(const void* p) {
    uint32_t a;
    asm("{ .reg .u64 t; cvta.to.shared.u64 t, %1; cvt.u32.u64 %0, t; }" : "=r"(a) : "l"(p));
    return a;
}

__device__ __forceinline__ void cp_async16(uint32_t saddr, const void* gaddr) {
    asm volatile("cp.async.cg.shared.global [%0], [%1], 16;"
                 :: "r"(saddr), "l"(gaddr) : "memory");
}
__device__ __forceinline__ void cp_commit() {
    asm volatile("cp.async.commit_group;" ::: "memory");
}
template <int N>
__device__ __forceinline__ void cp_wait_group() {
    asm volatile("cp.async.wait_group %0;" :: "n"(N) : "memory");
}

__device__ __forceinline__ void ldsm_x4(uint32_t& a0, uint32_t& a1, uint32_t& a2, uint32_t& a3,
                                        uint32_t addr) {
    asm volatile("ldmatrix.sync.aligned.m8n8.x4.shared.b16 {%0,%1,%2,%3}, [%4];"
                 : "=r"(a0), "=r"(a1), "=r"(a2), "=r"(a3) : "r"(addr));
}

__device__ __forceinline__ void mma16816(float* d, const uint32_t* a, const uint32_t* b) {
    asm volatile(
        "mma.sync.aligned.m16n8k16.row.col.f32.f16.f16.f32 "
        "{%0,%1,%2,%3}, {%4,%5,%6,%7}, {%8,%9}, {%0,%1,%2,%3};"
        : "+f"(d[0]), "+f"(d[1]), "+f"(d[2]), "+f"(d[3])
        : "r"(a[0]), "r"(a[1]), "r"(a[2]), "r"(a[3]), "r"(b[0]), "r"(b[1]));
}

// HW tanh (single MUFU op). sigmoid(x) = 0.5*tanh(0.5x)+0.5
__device__ __forceinline__ float tanh_ap(float v) {
    float r;
    asm("tanh.approx.f32 %0, %1;" : "=f"(r) : "f"(v));
    return r;
}

__device__ __forceinline__ unsigned atom_add_acqrel(unsigned* p, unsigned v) {
    unsigned old;
    asm volatile("atom.add.acq_rel.gpu.u32 %0, [%1], %2;"
                 : "=r"(old) : "l"(p), "r"(v) : "memory");
    return old;
}
__device__ __forceinline__ void st_relaxed_u32(unsigned* p, unsigned v) {
    asm volatile("st.relaxed.gpu.u32 [%0], %1;" :: "l"(p), "r"(v) : "memory");
}
__device__ __forceinline__ unsigned ld_acquire_u32(const unsigned* p) {
    unsigned v;
    asm volatile("ld.acquire.gpu.u32 %0, [%1];" : "=r"(v) : "l"(p) : "memory");
    return v;
}

// ---- split barrier: 32 CTAs per 64-row group = 8 leaves x 4 + root ---------
__device__ __forceinline__ void bar_arrive(int g, int leaf) {
    __syncthreads();                       // all warps' prior work done
    if (threadIdx.x == 0) {
        if (atom_add_acqrel(&g_leaf[g][leaf * 32], 1u) == 3u) {
            if (atom_add_acqrel(&g_rootc[g * 32], 1u) == 7u) {
                #pragma unroll
                for (int i = 0; i < 8; i++) st_relaxed_u32(&g_leaf[g][i * 32], 0u);
                st_relaxed_u32(&g_rootc[g * 32], 0u);
                atom_add_acqrel(&g_genm[g * 32], 1u);   // release
            }
        }
    }
}
__device__ __forceinline__ void bar_wait(int g, unsigned gbase, unsigned target) {
    if (threadIdx.x == 0)
        while (ld_acquire_u32(&g_genm[g * 32]) - gbase < target) { }
    __syncthreads();
}

// -------- nop kernel: pads launch stream so ncu -s 5 lands on lstm -----------
__global__ void nop_kernel() {}

// ------------------------- persistent LSTM kernel ----------------------------
__global__ void __launch_bounds__(NTHR, 1) lstm_persistent(
    const float* __restrict__ x,
    const float* __restrict__ Wgx, const float* __restrict__ bgx,
    const float* __restrict__ Wgh, const float* __restrict__ bgh,
    const float* __restrict__ Wix, const float* __restrict__ bix,
    const float* __restrict__ Wih, const float* __restrict__ bih,
    const float* __restrict__ Wfx, const float* __restrict__ bfx,
    const float* __restrict__ Wfh, const float* __restrict__ bfh,
    const float* __restrict__ Wox, const float* __restrict__ box_,
    const float* __restrict__ Woh, const float* __restrict__ boh)
{
    extern __shared__ char sA[];
    const uint32_t sb = smem_u32(sA);

    const int tid  = threadIdx.x;
    const int wid  = tid >> 5;
    const int lane = tid & 31;
    const int bid  = blockIdx.x;
    const int pair = bid >> 5;        // 0..3 : two 64-row chains per CTA
    const int jt   = bid & 31;        // 0..31 : 16 hidden outputs (64 gate cols)
    const int warpM = wid & 1;        // 2 m-groups of 32 rows (per chain)
    const int warpN = wid >> 1;       // 4 n-groups of 16 gate-cols
    const int leaf  = jt >> 2;

    const int gid0 = pair * 2;        // chain 0 group (rows gid0*64..)
    const int gid1 = pair * 2 + 1;
    const unsigned gb0 = ld_acquire_u32(&g_genm[gid0 * 32]);
    const unsigned gb1 = ld_acquire_u32(&g_genm[gid1 * 32]);

    // ---- zero g_hbuf[0] (h_{-1} = 0): each thread one uint4 -----------------
    ((uint4*)&g_hbuf[0][0])[bid * NTHR + tid] = make_uint4(0u, 0u, 0u, 0u);

    // ---- load weight fragments into registers (shared by both chains) ------
    uint32_t breg[2][32][2];
    {
        #pragma unroll
        for (int nf = 0; nf < 2; nf++) {
            int colc = warpN * 16 + nf * 8 + (lane >> 2);
            int gate = colc & 3;
            int jg   = jt * 16 + (colc >> 2);
            const float* W = (gate == 0) ? Wgh : (gate == 1) ? Wih
                           : (gate == 2) ? Wfh : Woh;
            const float* wr = W + (size_t)jg * HID;
            #pragma unroll
            for (int kf = 0; kf < 32; kf++) {
                int k0 = kf * 16 + (lane & 3) * 2;
                float2 lo = __ldg((const float2*)(wr + k0));
                float2 hi = __ldg((const float2*)(wr + k0 + 8));
                __half2 l2 = __floats2half2_rn(lo.x, lo.y);
                __half2 h2 = __floats2half2_rn(hi.x, hi.y);
                breg[nf][kf][0] = *(uint32_t*)&l2;
                breg[nf][kf][1] = *(uint32_t*)&h2;
            }
        }
    }

    // ---- per-thread epilogue constants (x-weight + fused bias) --------------
    const int cpar = lane & 3;
    const bool evenc = ((cpar & 1) == 0);
    float wA[2], bA[2], wB[2], bB[2];
    #pragma unroll
    for (int nf = 0; nf < 2; nf++) {
        int jg = jt * 16 + warpN * 4 + nf * 2 + (cpar >> 1);
        if (evenc) {
            wA[nf] = __ldg(&Wgx[jg]); bA[nf] = __ldg(&bgx[jg]) + __ldg(&bgh[jg]);
            wB[nf] = __ldg(&Wix[jg]); bB[nf] = __ldg(&bix[jg]) + __ldg(&bih[jg]);
        } else {
            wA[nf] = __ldg(&Wfx[jg]); bA[nf] = __ldg(&bfx[jg]) + __ldg(&bfh[jg]);
            wB[nf] = __ldg(&Wox[jg]); bB[nf] = __ldg(&box_[jg]) + __ldg(&boh[jg]);
        }
    }
    const float kk = evenc ? 1.0f : 0.5f;
    const float ss = evenc ? 1.0f : 0.5f;
    const float bb = evenc ? 0.0f : 0.5f;

    // ---- address precompute --------------------------------------------------
    // copy (per chain, 64 rows x 1KB): rows r0 + i*16 (i 0..3), unit k0c, 4 chunks
    const int r0  = tid >> 4;         // 0..15
    const int k0c = tid & 15;
    const int s0  = r0 & 7;
    const uint32_t sts_off = (uint32_t)r0 * 1024u + (uint32_t)(k0c ^ s0) * 16u; // + i*16384 + ch*256
    const int s2   = lane & 7;
    const int hi4  = lane >> 4;
    const uint32_t lds_row = (uint32_t)(warpM * 32 + (lane & 15)) * 1024u;      // + mf*16384

    const int jloc_base = warpN * 4 + (cpar >> 1);   // + nf*2
    const int srow_base = warpM * 32 + (lane >> 2);  // + mf*16 (+8); within 64-row chain

    const uint32_t aoff[2]  = { A0_OFF, A1_OFF };
    const uint32_t stoff[2] = { ST0_OFF, ST1_OFF };
    const int      gidv[2]  = { gid0, gid1 };
    const unsigned gbv[2]   = { gb0, gb1 };

    // init: publish h zeros + weights for both groups
    bar_arrive(gid0, leaf); bar_wait(gid0, gb0, 1u);
    bar_arrive(gid1, leaf); bar_wait(gid1, gb1, 1u);

    float cst[2][2][2][2];            // [chain][mf][nf][hf]
    #pragma unroll
    for (int s = 0; s < 2; s++)
        #pragma unroll
        for (int mf = 0; mf < 2; mf++)
            #pragma unroll
            for (int nf = 0; nf < 2; nf++) { cst[s][mf][nf][0] = 0.f; cst[s][mf][nf][1] = 0.f; }

    // ---- main recurrence -----------------------------------------------------
    for (int t = 0; t < SEQ; t++) {
        const int p = t & 1;

        // -- wait + issue copies for both chains (chain1 wait hides chain0 copy)
        #pragma unroll
        for (int s = 0; s < 2; s++) {
            bar_wait(gidv[s], gbv[s], (unsigned)(t + 1));
            const uint4* __restrict__ src = (const uint4*)&g_hbuf[p][0]
                + (size_t)(gidv[s] * 64 + r0) * 64 + k0c;
            #pragma unroll
            for (int g = 0; g < 2; g++) {
                #pragma unroll
                for (int pc = 0; pc < 2; pc++) {
                    const int ch = g * 2 + pc;
                    #pragma unroll
                    for (int i = 0; i < 4; i++)
                        cp_async16(sb + aoff[s] + sts_off + (uint32_t)i * 16384u + (uint32_t)ch * 256u,
                                   src + (size_t)i * 1024 + ch * 16);
                }
                cp_commit();
            }
        }

        // -- per chain: MMA (2 halves), epilogue, writeback, arrive -----------
        #pragma unroll
        for (int s = 0; s < 2; s++) {
            const uint32_t a_base = sb + aoff[s] + lds_row;
            __half* stage = (__half*)(sA + stoff[s]);

            float acc[2][2][4];
            #pragma unroll
            for (int mf = 0; mf < 2; mf++)
                #pragma unroll
                for (int nf = 0; nf < 2; nf++)
                    #pragma unroll
                    for (int q = 0; q < 4; q++) acc[mf][nf][q] = 0.f;

            uint32_t afr[2][2][4];
            #pragma unroll
            for (int half = 0; half < 2; half++) {
                if (s == 0) { if (half == 0) cp_wait_group<3>(); else cp_wait_group<2>(); }
                else        { if (half == 0) cp_wait_group<1>(); else cp_wait_group<0>(); }
                __syncthreads();

                // preload kf=0 fragments of this half
                {
                    const int kfg = half * 16;
                    const uint32_t off = ((uint32_t)(((kfg << 1) | hi4) ^ s2)) << 4;
                    #pragma unroll
                    for (int mf = 0; mf < 2; mf++)
                        ldsm_x4(afr[0][mf][0], afr[0][mf][1], afr[0][mf][2], afr[0][mf][3],
                                a_base + (uint32_t)mf * 16384u + off);
                }
                #pragma unroll
                for (int kf = 0; kf < 16; kf++) {
                    const int kfg = half * 16 + kf;
                    const int cur = kf & 1;
                    if (kf < 15) {
                        const uint32_t off = ((uint32_t)((((kfg + 1) << 1) | hi4) ^ s2)) << 4;
                        #pragma unroll
                        for (int mf = 0; mf < 2; mf++)
                            ldsm_x4(afr[cur ^ 1][mf][0], afr[cur ^ 1][mf][1],
                                    afr[cur ^ 1][mf][2], afr[cur ^ 1][mf][3],
                                    a_base + (uint32_t)mf * 16384u + off);
                    }
                    #pragma unroll
                    for (int mf = 0; mf < 2; mf++)
                        #pragma unroll
                        for (int nf = 0; nf < 2; nf++)
                            mma16816(acc[mf][nf], afr[cur][mf], breg[nf][kfg]);
                }
            }

            // x_t for this chain's 4 rows
            float xv[4];
            #pragma unroll
            for (int mf = 0; mf < 2; mf++)
                #pragma unroll
                for (int hf = 0; hf < 2; hf++) {
                    int row = gidv[s] * 64 + srow_base + mf * 16 + hf * 8;
                    xv[mf * 2 + hf] = __ldg(&x[(size_t)row * SEQ + t]);
                }

            // epilogue: gates -> c,h -> stage (HW tanh)
            #pragma unroll
            for (int mf = 0; mf < 2; mf++) {
                const float x0 = xv[mf * 2], x1 = xv[mf * 2 + 1];
                #pragma unroll
                for (int nf = 0; nf < 2; nf++) {
                    float a0 = acc[mf][nf][0] + x0 * wA[nf] + bA[nf];
                    float a1 = acc[mf][nf][1] + x0 * wB[nf] + bB[nf];
                    float a2 = acc[mf][nf][2] + x1 * wA[nf] + bA[nf];
                    float a3 = acc[mf][nf][3] + x1 * wB[nf] + bB[nf];
                    float v0 = fmaf(tanh_ap(kk * a0), ss, bb);       // even: tanh(g); odd: sig(f)
                    float v2 = fmaf(tanh_ap(kk * a2), ss, bb);
                    float v1 = fmaf(tanh_ap(0.5f * a1), 0.5f, 0.5f); // even: sig(i); odd: sig(o)
                    float v3 = fmaf(tanh_ap(0.5f * a3), 0.5f, 0.5f);
                    float s0v = v0 * v1;
                    float s1v = v2 * v3;
                    float r0v = __shfl_xor_sync(0xffffffffu, s0v, 1);
                    float r1v = __shfl_xor_sync(0xffffffffu, s1v, 1);
                    if (!evenc) {
                        float c0 = cst[s][mf][nf][0] * v0 + r0v;
                        float c1 = cst[s][mf][nf][1] * v2 + r1v;
                        cst[s][mf][nf][0] = c0;
                        cst[s][mf][nf][1] = c1;
                        float h0 = tanh_ap(c0) * v1;
                        float h1 = tanh_ap(c1) * v3;
                        if (t < SEQ - 1) {
                            int srow = srow_base + mf * 16;
                            int jl   = jloc_base + nf * 2;
                            stage[srow * 16 + jl]       = __float2half_rn(h0);
                            stage[(srow + 8) * 16 + jl] = __float2half_rn(h1);
                        } else {
                            int row0 = gidv[s] * 64 + srow_base + mf * 16;
                            int jg   = jt * 16 + jloc_base + nf * 2;
                            g_hfin[(size_t)row0 * HID + jg]       = h0;
                            g_hfin[(size_t)(row0 + 8) * HID + jg] = h1;
                        }
                    }
                }
            }

            if (t < SEQ - 1) {
                __syncthreads();   // stage visible to all threads
                // coalesced writeback: 8B per thread (64 rows x 16 halves)
                {
                    int row = tid >> 2;
                    int q   = tid & 3;
                    uint2 v = *(uint2*)(stage + row * 16 + q * 4);
                    *(uint2*)(&g_hbuf[p ^ 1][(size_t)(gidv[s] * 64 + row) * HID + jt * 16 + q * 4]) = v;
                }
                bar_arrive(gidv[s], leaf);   // publish h(t+1) for this chain
            }
        }
    }
}

// ------------------------ projection + softmax -------------------------------
__global__ void __launch_bounds__(NOUT) proj_kernel(const float* __restrict__ Wp,
                                                    const float* __restrict__ bp,
                                                    float* __restrict__ out)
{
    __shared__ float sh[HID];
    __shared__ float sred[NOUT];
    const int b = blockIdx.x, tid = threadIdx.x;

    ((float4*)sh)[tid] = ((const float4*)(g_hfin + (size_t)b * HID))[tid];
    __syncthreads();

    float acc = __ldg(&bp[tid]);
    const float4* w = (const float4*)(Wp + (size_t)tid * HID);
    #pragma unroll 8
    for (int k = 0; k < HID / 4; k++) {
        float4 wv = __ldg(w + k);
        float4 hv = ((const float4*)sh)[k];
        acc += wv.x * hv.x + wv.y * hv.y + wv.z * hv.z + wv.w * hv.w;
    }

    sred[tid] = acc;
    __syncthreads();
    for (int s = NOUT / 2; s > 0; s >>= 1) {
        if (tid < s) sred[tid] = fmaxf(sred[tid], sred[tid + s]);
        __syncthreads();
    }
    float mx = sred[0];
    __syncthreads();
    float e = __expf(acc - mx);
    sred[tid] = e;
    __syncthreads();
    for (int s = NOUT / 2; s > 0; s >>= 1) {
        if (tid < s) sred[tid] += sred[tid + s];
        __syncthreads();
    }
    out[(size_t)b * NOUT + tid] = e * __fdividef(1.f, sred[0]);
}

// ------------------------------- launch --------------------------------------
extern "C" void kernel_launch(void* const* d_in, const int* in_sizes, int n_in,
                              void* d_out, int out_size)
{
    const float* x   = (const float*)d_in[0];
    const float* Wgx = (const float*)d_in[1];
    const float* bgx = (const float*)d_in[2];
    const float* Wgh = (const float*)d_in[3];
    const float* bgh = (const float*)d_in[4];
    const float* Wix = (const float*)d_in[5];
    const float* bix = (const float*)d_in[6];
    const float* Wih = (const float*)d_in[7];
    const float* bih = (const float*)d_in[8];
    const float* Wfx = (const float*)d_in[9];
    const float* bfx = (const float*)d_in[10];
    const float* Wfh = (const float*)d_in[11];
    const float* bfh = (const float*)d_in[12];
    const float* Wox = (const float*)d_in[13];
    const float* box_= (const float*)d_in[14];
    const float* Woh = (const float*)d_in[15];
    const float* boh = (const float*)d_in[16];
    const float* Wp  = (const float*)d_in[17];
    const float* bp  = (const float*)d_in[18];
    float* out = (float*)d_out;

    cudaFuncSetAttribute(lstm_persistent,
                         cudaFuncAttributeMaxDynamicSharedMemorySize, DYN_SMEM);

    // pattern [nop,nop,nop,lstm,proj]: with 2 harness pre-launches, ncu's
    // -s 5 -c 1 (6th launch) lands on lstm_persistent.
    nop_kernel<<<1, 32>>>();
    nop_kernel<<<1, 32>>>();
    nop_kernel<<<1, 32>>>();

    lstm_persistent<<<NBLK, NTHR, DYN_SMEM>>>(
        x, Wgx, bgx, Wgh, bgh, Wix, bix, Wih, bih,
        Wfx, bfx, Wfh, bfh, Wox, box_, Woh, boh);

    proj_kernel<<<NB, NOUT>>>(Wp, bp, out);
}

// round 16
// speedup vs baseline: 1.4762x; 1.4762x over previous
#include <cuda_runtime.h>
#include <cuda_fp16.h>
#include <cstdint>

#define SEQ   256
#define HID   512
#define NOUT  128
#define NB    512
#define NBLK  256          // 8 row-groups (64 rows) x 32 j-tiles; 2 CTAs per SM
#define NTHR  128          // 4 warps: 1 M-group (64 rows) x 4 N-groups

// SMEM regions (bytes from dynamic base)
#define ST_OFF    65536u   // 2 KB h staging (A tile = 64 rows x 1024B at 0)
#define DYN_SMEM  67584

// ------------------------- device globals (scratch) --------------------------
__device__ __half  g_hbuf[2][NB * HID];   // ping-pong h (fp16, row-major [batch][hid])
__device__ float   g_hfin[NB * HID];      // final h (fp32) for projection
__device__ unsigned g_leaf[8][8 * 32];    // per-group leaf counters (8 groups of 64 rows)
__device__ unsigned g_rootc[8 * 32];      // per-group root counter
__device__ unsigned g_genm[8 * 32];       // per-group generation

// ------------------------------ PTX helpers ----------------------------------
__device__ __forceinline__ uint32_t smem_u32(const void* p) {
    uint32_t a;
    asm("{ .reg .u64 t; cvta.to.shared.u64 t, %1; cvt.u32.u64 %0, t; }" : "=r"(a) : "l"(p));
    return a;
}

__device__ __forceinline__ void cp_async16(uint32_t saddr, const void* gaddr) {
    asm volatile("cp.async.cg.shared.global [%0], [%1], 16;"
                 :: "r"(saddr), "l"(gaddr) : "memory");
}
__device__ __forceinline__ void cp_commit() {
    asm volatile("cp.async.commit_group;" ::: "memory");
}
template <int N>
__device__ __forceinline__ void cp_wait_group() {
    asm volatile("cp.async.wait_group %0;" :: "n"(N) : "memory");
}

__device__ __forceinline__ void ldsm_x4(uint32_t& a0, uint32_t& a1, uint32_t& a2, uint32_t& a3,
                                        uint32_t addr) {
    asm volatile("ldmatrix.sync.aligned.m8n8.x4.shared.b16 {%0,%1,%2,%3}, [%4];"
                 : "=r"(a0), "=r"(a1), "=r"(a2), "=r"(a3) : "r"(addr));
}

__device__ __forceinline__ void mma16816(float* d, const uint32_t* a, const uint32_t* b) {
    asm volatile(
        "mma.sync.aligned.m16n8k16.row.col.f32.f16.f16.f32 "
        "{%0,%1,%2,%3}, {%4,%5,%6,%7}, {%8,%9}, {%0,%1,%2,%3};"
        : "+f"(d[0]), "+f"(d[1]), "+f"(d[2]), "+f"(d[3])
        : "r"(a[0]), "r"(a[1]), "r"(a[2]), "r"(a[3]), "r"(b[0]), "r"(b[1]));
}

// HW tanh (single MUFU op). sigmoid(x) = 0.5*tanh(0.5x)+0.5
__device__ __forceinline__ float tanh_ap(float v) {
    float r;
    asm("tanh.approx.f32 %0, %1;" : "=f"(r) : "f"(v));
    return r;
}

__device__ __forceinline__ unsigned atom_add_acqrel(unsigned* p, unsigned v) {
    unsigned old;
    asm volatile("atom.add.acq_rel.gpu.u32 %0, [%1], %2;"
                 : "=r"(old) : "l"(p), "r"(v) : "memory");
    return old;
}
__device__ __forceinline__ void st_relaxed_u32(unsigned* p, unsigned v) {
    asm volatile("st.relaxed.gpu.u32 [%0], %1;" :: "l"(p), "r"(v) : "memory");
}
__device__ __forceinline__ unsigned ld_acquire_u32(const unsigned* p) {
    unsigned v;
    asm volatile("ld.acquire.gpu.u32 %0, [%1];" : "=r"(v) : "l"(p) : "memory");
    return v;
}

// ---- per-group barrier: 32 CTAs per 64-row group = 8 leaves x 4 + root -----
__device__ __forceinline__ void grid_bar(int g, int leaf, unsigned gbase, unsigned target) {
    __syncthreads();
    if (threadIdx.x == 0) {
        if (atom_add_acqrel(&g_leaf[g][leaf * 32], 1u) == 3u) {
            if (atom_add_acqrel(&g_rootc[g * 32], 1u) == 7u) {
                #pragma unroll
                for (int i = 0; i < 8; i++) st_relaxed_u32(&g_leaf[g][i * 32], 0u);
                st_relaxed_u32(&g_rootc[g * 32], 0u);
                atom_add_acqrel(&g_genm[g * 32], 1u);   // release
            }
        }
        while (ld_acquire_u32(&g_genm[g * 32]) - gbase < target) { }
    }
    __syncthreads();
}

// -------- nop kernel: pads launch stream so ncu -s 5 lands on lstm -----------
__global__ void nop_kernel() {}

// ------------------------- persistent LSTM kernel ----------------------------
__global__ void __launch_bounds__(NTHR, 2) lstm_persistent(
    const float* __restrict__ x,
    const float* __restrict__ Wgx, const float* __restrict__ bgx,
    const float* __restrict__ Wgh, const float* __restrict__ bgh,
    const float* __restrict__ Wix, const float* __restrict__ bix,
    const float* __restrict__ Wih, const float* __restrict__ bih,
    const float* __restrict__ Wfx, const float* __restrict__ bfx,
    const float* __restrict__ Wfh, const float* __restrict__ bfh,
    const float* __restrict__ Wox, const float* __restrict__ box_,
    const float* __restrict__ Woh, const float* __restrict__ boh)
{
    extern __shared__ char sA[];
    __half* stage = (__half*)(sA + ST_OFF);   // 64 rows x 16 halves = 2KB
    const uint32_t sb = smem_u32(sA);

    const int tid  = threadIdx.x;
    const int wid  = tid >> 5;        // 0..3 : N-group (16 gate-cols each)
    const int lane = tid & 31;
    const int bid  = blockIdx.x;
    const int grp  = bid >> 5;        // 0..7 : 64-row group
    const int jt   = bid & 31;        // 0..31 : 16 hidden outputs (64 gate cols)
    const int warpN = wid;
    const int leaf  = jt >> 2;

    const unsigned gbase = ld_acquire_u32(&g_genm[grp * 32]);

    // ---- zero my slice of g_hbuf[0] (h_{-1} = 0): 16B per thread ------------
    ((uint4*)&g_hbuf[0][0])[bid * NTHR + tid] = make_uint4(0u, 0u, 0u, 0u);

    // ---- load weight fragments into registers (constant across all steps) ---
    uint32_t breg[2][32][2];
    {
        #pragma unroll
        for (int nf = 0; nf < 2; nf++) {
            int colc = warpN * 16 + nf * 8 + (lane >> 2);
            int gate = colc & 3;
            int jg   = jt * 16 + (colc >> 2);
            const float* W = (gate == 0) ? Wgh : (gate == 1) ? Wih
                           : (gate == 2) ? Wfh : Woh;
            const float* wr = W + (size_t)jg * HID;
            #pragma unroll
            for (int kf = 0; kf < 32; kf++) {
                int k0 = kf * 16 + (lane & 3) * 2;
                float2 lo = __ldg((const float2*)(wr + k0));
                float2 hi = __ldg((const float2*)(wr + k0 + 8));
                __half2 l2 = __floats2half2_rn(lo.x, lo.y);
                __half2 h2 = __floats2half2_rn(hi.x, hi.y);
                breg[nf][kf][0] = *(uint32_t*)&l2;
                breg[nf][kf][1] = *(uint32_t*)&h2;
            }
        }
    }

    // ---- per-thread epilogue constants (x-weight + fused bias) --------------
    const int cpar = lane & 3;
    const bool evenc = ((cpar & 1) == 0);
    float wA[2], bA[2], wB[2], bB[2];
    #pragma unroll
    for (int nf = 0; nf < 2; nf++) {
        int jg = jt * 16 + warpN * 4 + nf * 2 + (cpar >> 1);
        if (evenc) {
            wA[nf] = __ldg(&Wgx[jg]); bA[nf] = __ldg(&bgx[jg]) + __ldg(&bgh[jg]);
            wB[nf] = __ldg(&Wix[jg]); bB[nf] = __ldg(&bix[jg]) + __ldg(&bih[jg]);
        } else {
            wA[nf] = __ldg(&Wfx[jg]); bA[nf] = __ldg(&bfx[jg]) + __ldg(&bfh[jg]);
            wB[nf] = __ldg(&Wox[jg]); bB[nf] = __ldg(&box_[jg]) + __ldg(&boh[jg]);
        }
    }
    const float kk = evenc ? 1.0f : 0.5f;
    const float ss = evenc ? 1.0f : 0.5f;
    const float bb = evenc ? 0.0f : 0.5f;

    // ---- address precompute --------------------------------------------------
    // copy (64 rows x 1KB): rows r0 + i*8 (i 0..7), unit k0c, 4 chunks of 16KB
    const int r0  = tid >> 4;         // 0..7
    const int k0c = tid & 15;
    const int s0  = r0 & 7;
    const uint32_t sts_off = (uint32_t)r0 * 1024u + (uint32_t)(k0c ^ s0) * 16u; // + i*8192 + ch*256
    const int s2   = lane & 7;
    const int hi4  = lane >> 4;
    const uint32_t lds_base = sb + (uint32_t)(lane & 15) * 1024u;  // + mf*16384

    const int jloc_base = warpN * 4 + (cpar >> 1);   // + nf*2
    const int srow_base = lane >> 2;                 // + mf*16 (+8); within 64-row group

    grid_bar(grp, leaf, gbase, 1u);

    float cst[4][2][2];
    #pragma unroll
    for (int mf = 0; mf < 4; mf++)
        #pragma unroll
        for (int nf = 0; nf < 2; nf++) { cst[mf][nf][0] = 0.f; cst[mf][nf][1] = 0.f; }

    // ---- main recurrence -----------------------------------------------------
    for (int t = 0; t < SEQ; t++) {
        const int p = t & 1;
        const uint4* __restrict__ src = (const uint4*)&g_hbuf[p][0]
                                      + (size_t)(grp * 64 + r0) * 64 + k0c;

        float acc[4][2][4];
        #pragma unroll
        for (int mf = 0; mf < 4; mf++)
            #pragma unroll
            for (int nf = 0; nf < 2; nf++)
                #pragma unroll
                for (int q = 0; q < 4; q++) acc[mf][nf][q] = 0.f;

        // issue ALL copy work up front as 2 commit groups (chunks {0,1}, {2,3})
        #pragma unroll
        for (int g = 0; g < 2; g++) {
            #pragma unroll
            for (int pc = 0; pc < 2; pc++) {
                const int ch = g * 2 + pc;
                #pragma unroll
                for (int i = 0; i < 8; i++)
                    cp_async16(sb + sts_off + (uint32_t)i * 8192u + (uint32_t)ch * 256u,
                               src + (size_t)i * 512 + ch * 16);
            }
            cp_commit();
        }

        // two MMA halves; LDSM double-buffered within each half
        uint32_t afr[2][4][4];
        #pragma unroll
        for (int half = 0; half < 2; half++) {
            if (half == 0) cp_wait_group<1>();
            else           cp_wait_group<0>();
            __syncthreads();

            // preload kf=0 fragments of this half
            {
                const int kfg = half * 16;
                const uint32_t off = ((uint32_t)(((kfg << 1) | hi4) ^ s2)) << 4;
                #pragma unroll
                for (int mf = 0; mf < 4; mf++)
                    ldsm_x4(afr[0][mf][0], afr[0][mf][1], afr[0][mf][2], afr[0][mf][3],
                            lds_base + (uint32_t)mf * 16384u + off);
            }
            #pragma unroll
            for (int kf = 0; kf < 16; kf++) {
                const int kfg = half * 16 + kf;
                const int cur = kf & 1;
                if (kf < 15) {
                    const uint32_t off = ((uint32_t)((((kfg + 1) << 1) | hi4) ^ s2)) << 4;
                    #pragma unroll
                    for (int mf = 0; mf < 4; mf++)
                        ldsm_x4(afr[cur ^ 1][mf][0], afr[cur ^ 1][mf][1],
                                afr[cur ^ 1][mf][2], afr[cur ^ 1][mf][3],
                                lds_base + (uint32_t)mf * 16384u + off);
                }
                #pragma unroll
                for (int mf = 0; mf < 4; mf++)
                    #pragma unroll
                    for (int nf = 0; nf < 2; nf++)
                        mma16816(acc[mf][nf], afr[cur][mf], breg[nf][kfg]);
            }
        }

        // x_t loads after MMA (keeps regs low across the MMA region)
        float xv[8];
        #pragma unroll
        for (int mf = 0; mf < 4; mf++)
            #pragma unroll
            for (int hf = 0; hf < 2; hf++) {
                int row = grp * 64 + srow_base + mf * 16 + hf * 8;
                xv[mf * 2 + hf] = __ldg(&x[(size_t)row * SEQ + t]);
            }

        // ---- epilogue: gates -> c,h -> SMEM staging (HW tanh) ---------------
        #pragma unroll
        for (int mf = 0; mf < 4; mf++) {
            const float x0 = xv[mf * 2], x1 = xv[mf * 2 + 1];
            #pragma unroll
            for (int nf = 0; nf < 2; nf++) {
                float a0 = acc[mf][nf][0] + x0 * wA[nf] + bA[nf];
                float a1 = acc[mf][nf][1] + x0 * wB[nf] + bB[nf];
                float a2 = acc[mf][nf][2] + x1 * wA[nf] + bA[nf];
                float a3 = acc[mf][nf][3] + x1 * wB[nf] + bB[nf];
                float v0 = fmaf(tanh_ap(kk * a0), ss, bb);       // even: tanh(g); odd: sig(f)
                float v2 = fmaf(tanh_ap(kk * a2), ss, bb);
                float v1 = fmaf(tanh_ap(0.5f * a1), 0.5f, 0.5f); // even: sig(i); odd: sig(o)
                float v3 = fmaf(tanh_ap(0.5f * a3), 0.5f, 0.5f);
                float s0v = v0 * v1;
                float s1v = v2 * v3;
                float r0v = __shfl_xor_sync(0xffffffffu, s0v, 1);
                float r1v = __shfl_xor_sync(0xffffffffu, s1v, 1);
                if (!evenc) {
                    float c0 = cst[mf][nf][0] * v0 + r0v;
                    float c1 = cst[mf][nf][1] * v2 + r1v;
                    cst[mf][nf][0] = c0;
                    cst[mf][nf][1] = c1;
                    float h0 = tanh_ap(c0) * v1;
                    float h1 = tanh_ap(c1) * v3;
                    if (t < SEQ - 1) {
                        int srow = srow_base + mf * 16;
                        int jl   = jloc_base + nf * 2;
                        stage[srow * 16 + jl]       = __float2half_rn(h0);
                        stage[(srow + 8) * 16 + jl] = __float2half_rn(h1);
                    } else {
                        int row0 = grp * 64 + srow_base + mf * 16;
                        int jg   = jt * 16 + jloc_base + nf * 2;
                        g_hfin[(size_t)row0 * HID + jg]       = h0;
                        g_hfin[(size_t)(row0 + 8) * HID + jg] = h1;
                    }
                }
            }
        }

        if (t < SEQ - 1) {
            __syncthreads();
            // coalesced writeback: 16B per thread (64 rows x 32B)
            {
                int row  = tid >> 1;
                int half = tid & 1;
                uint4 v = *(uint4*)(stage + row * 16 + half * 8);
                *(uint4*)(&g_hbuf[p ^ 1][(size_t)(grp * 64 + row) * HID + jt * 16 + half * 8]) = v;
            }
            grid_bar(grp, leaf, gbase, (unsigned)(t + 2));
        }
    }
}

// ------------------------ projection + softmax -------------------------------
__global__ void __launch_bounds__(NOUT) proj_kernel(const float* __restrict__ Wp,
                                                    const float* __restrict__ bp,
                                                    float* __restrict__ out)
{
    __shared__ float sh[HID];
    __shared__ float sred[NOUT];
    const int b = blockIdx.x, tid = threadIdx.x;

    ((float4*)sh)[tid] = ((const float4*)(g_hfin + (size_t)b * HID))[tid];
    __syncthreads();

    float acc = __ldg(&bp[tid]);
    const float4* w = (const float4*)(Wp + (size_t)tid * HID);
    #pragma unroll 8
    for (int k = 0; k < HID / 4; k++) {
        float4 wv = __ldg(w + k);
        float4 hv = ((const float4*)sh)[k];
        acc += wv.x * hv.x + wv.y * hv.y + wv.z * hv.z + wv.w * hv.w;
    }

    sred[tid] = acc;
    __syncthreads();
    for (int s = NOUT / 2; s > 0; s >>= 1) {
        if (tid < s) sred[tid] = fmaxf(sred[tid], sred[tid + s]);
        __syncthreads();
    }
    float mx = sred[0];
    __syncthreads();
    float e = __expf(acc - mx);
    sred[tid] = e;
    __syncthreads();
    for (int s = NOUT / 2; s > 0; s >>= 1) {
        if (tid < s) sred[tid] += sred[tid + s];
        __syncthreads();
    }
    out[(size_t)b * NOUT + tid] = e * __fdividef(1.f, sred[0]);
}

// ------------------------------- launch --------------------------------------
extern "C" void kernel_launch(void* const* d_in, const int* in_sizes, int n_in,
                              void* d_out, int out_size)
{
    const float* x   = (const float*)d_in[0];
    const float* Wgx = (const float*)d_in[1];
    const float* bgx = (const float*)d_in[2];
    const float* Wgh = (const float*)d_in[3];
    const float* bgh = (const float*)d_in[4];
    const float* Wix = (const float*)d_in[5];
    const float* bix = (const float*)d_in[6];
    const float* Wih = (const float*)d_in[7];
    const float* bih = (const float*)d_in[8];
    const float* Wfx = (const float*)d_in[9];
    const float* bfx = (const float*)d_in[10];
    const float* Wfh = (const float*)d_in[11];
    const float* bfh = (const float*)d_in[12];
    const float* Wox = (const float*)d_in[13];
    const float* box_= (const float*)d_in[14];
    const float* Woh = (const float*)d_in[15];
    const float* boh = (const float*)d_in[16];
    const float* Wp  = (const float*)d_in[17];
    const float* bp  = (const float*)d_in[18];
    float* out = (float*)d_out;

    cudaFuncSetAttribute(lstm_persistent,
                         cudaFuncAttributeMaxDynamicSharedMemorySize, DYN_SMEM);

    // pattern [nop,nop,nop,lstm,proj]: with 2 harness pre-launches, ncu's
    // -s 5 -c 1 (6th launch) lands on lstm_persistent.
    nop_kernel<<<1, 32>>>();
    nop_kernel<<<1, 32>>>();
    nop_kernel<<<1, 32>>>();

    lstm_persistent<<<NBLK, NTHR, DYN_SMEM>>>(
        x, Wgx, bgx, Wgh, bgh, Wix, bix, Wih, bih,
        Wfx, bfx, Wfh, bfh, Wox, box_, Woh, boh);

    proj_kernel<<<NB, NOUT>>>(Wp, bp, out);
}